// round 2
// baseline (speedup 1.0000x reference)
#include <cuda_runtime.h>
#include <cstdint>

// Shapes (fixed for this problem)
#define BATCH 256
#define TT    2048
#define OBD   128
#define SD    128
#define HD    128
#define AD    32
#define YW    288   // [0:128)=Ys (y@BK2), [128:256)=Yv (y@DK3), [256:288)=Yu (y@DK2)

// 604 MB scratch for the time-parallel precompute
__device__ float g_Y[(size_t)BATCH * TT * YW];

// ---------------------------------------------------------------------------
// cp.async helpers
// ---------------------------------------------------------------------------
__device__ __forceinline__ void cp16(void* s, const void* g) {
    unsigned saddr = (unsigned)__cvta_generic_to_shared(s);
    asm volatile("cp.async.cg.shared.global [%0], [%1], 16;\n" :: "r"(saddr), "l"(g));
}
__device__ __forceinline__ void cp_commit() { asm volatile("cp.async.commit_group;\n"); }
__device__ __forceinline__ void cp_wait0()  { asm volatile("cp.async.wait_group 0;\n"); }

// Accurate tanh independent of --use_fast_math: (e^{2v}-1)/(e^{2v}+1) via MUFU EX2
__device__ __forceinline__ float tanh_acc(float x) {
    float xc = fminf(fmaxf(x, -15.f), 15.f);
    float e  = exp2f(xc * 2.8853900817779268f);   // 2*log2(e)
    return (e - 1.f) / (e + 1.f);
}

// ---------------------------------------------------------------------------
// Kernel 1: Y[m][0:288] = obs[m][:] @ [BK2 | DK3 | DK2]^T,  m = b*T + t
// Weights resident in smem (147 KB); obs double-buffered 32-row chunks.
// 288 threads: thread n owns output column n, 32 accumulators (rows).
// ---------------------------------------------------------------------------
__global__ __launch_bounds__(288, 1)
void precompute_y_kernel(const float* __restrict__ obs,
                         const float* __restrict__ BK2,
                         const float* __restrict__ DK3,
                         const float* __restrict__ DK2)
{
    extern __shared__ float sm[];
    float* W1  = sm;                 // [128][288]
    float* ob0 = sm + 128 * 288;     // [32][128]
    float* ob1 = ob0 + 32 * 128;

    const int tid = threadIdx.x;

    // Load combined W1 (one-time)
    for (int idx = tid; idx < 128 * 288; idx += 288) {
        int o = idx / 288, n = idx - o * 288;
        float v;
        if      (n < 128) v = BK2[o * 128 + n];
        else if (n < 256) v = DK3[o * 128 + (n - 128)];
        else              v = DK2[o * 32  + (n - 256)];
        W1[idx] = v;
    }

    const int NCH = (BATCH * TT) / 32;   // 16384 chunks of 32 rows
    int chunk = blockIdx.x;

    // Prologue: load first chunk into ob0
    {
        const float* src = obs + (size_t)chunk * 32 * 128;
        for (int i = tid; i < 1024; i += 288)          // 1024 float4 = 16 KB
            cp16(&ob0[i * 4], &src[i * 4]);
        cp_commit(); cp_wait0();
    }
    __syncthreads();

    int p = 0;
    for (; chunk < NCH; chunk += gridDim.x) {
        float* cur = p ? ob1 : ob0;
        float* nb  = p ? ob0 : ob1;
        int nxt = chunk + gridDim.x;
        if (nxt < NCH) {
            const float* src = obs + (size_t)nxt * 32 * 128;
            for (int i = tid; i < 1024; i += 288)
                cp16(&nb[i * 4], &src[i * 4]);
        }
        cp_commit();

        // Compute 32 rows x 1 column per thread
        float acc[32];
        #pragma unroll
        for (int m = 0; m < 32; m++) acc[m] = 0.f;
        const int n = tid;
        #pragma unroll 1
        for (int k = 0; k < 128; k += 4) {
            float w0 = W1[(k    ) * 288 + n];
            float w1 = W1[(k + 1) * 288 + n];
            float w2 = W1[(k + 2) * 288 + n];
            float w3 = W1[(k + 3) * 288 + n];
            #pragma unroll
            for (int m = 0; m < 32; m++) {
                float4 o = *(const float4*)&cur[m * 128 + k];
                acc[m] = fmaf(o.w, w3, fmaf(o.z, w2, fmaf(o.y, w1, fmaf(o.x, w0, acc[m]))));
            }
        }
        size_t base = (size_t)chunk * 32 * YW + n;
        #pragma unroll 4
        for (int m = 0; m < 32; m++)
            g_Y[base + (size_t)m * YW] = acc[m];

        cp_wait0();
        __syncthreads();
        p ^= 1;
    }
}

// ---------------------------------------------------------------------------
// Kernel 2: the sequential recurrence. 128 persistent CTAs x 2 batch rows,
// 160 threads, all weights in smem (exact 232448 B fit).
//   threads 0..127: phase A column h (v,z for both rows) + BC column c
//   threads 128..159: BC columns 128..159 (u) + direct d_out stores
// ---------------------------------------------------------------------------
__global__ __launch_bounds__(160, 1)
void rnn_seq_kernel(const float* __restrict__ state0,
                    const float* __restrict__ AK,
                    const float* __restrict__ BK1,
                    const float* __restrict__ CK1,
                    const float* __restrict__ DK1,
                    const float* __restrict__ CK2,
                    const float* __restrict__ logstd,
                    float* __restrict__ out)
{
    extern __shared__ float sm[];
    float* CK2s = sm;                  // [128][128]   v-phase weights
    float* W2   = sm + 16384;          // [256][160]   [AK|CK1 ; BK1|DK1]
    float* stA  = W2 + 40960;          // [128][2]     state ping (interleaved rows)
    float* stB  = stA + 256;           // [128][2]     state pong
    float* zs   = stB + 256;           // [128][2]     z (interleaved rows)

    const int tid = threadIdx.x;
    const int b0 = blockIdx.x * 2, b1 = b0 + 1;

    // One-time weight staging
    for (int idx = tid; idx < 16384; idx += 160) CK2s[idx] = CK2[idx];
    for (int idx = tid; idx < 40960; idx += 160) {
        int k = idx / 160, c = idx - k * 160;
        float v;
        if (k < 128) v = (c < 128) ? AK[k * 128 + c]  : CK1[k * 32 + (c - 128)];
        else { int j = k - 128;
               v = (c < 128) ? BK1[j * 128 + c] : DK1[j * 32 + (c - 128)]; }
        W2[idx] = v;
    }
    if (tid < 128) {
        stA[2 * tid]     = state0[b0 * 128 + tid];
        stA[2 * tid + 1] = state0[b1 * 128 + tid];
    }
    float ls = 0.f;
    if (tid >= 128) ls = logstd[tid - 128];
    __syncthreads();

    const float* Y0 = g_Y + (size_t)b0 * TT * YW;
    const float* Y1 = g_Y + (size_t)b1 * TT * YW;

    // Register prefetch of Y for t=0
    float yv0 = 0.f, yv1 = 0.f, ys0, ys1;
    if (tid < 128) {
        yv0 = Y0[128 + tid]; yv1 = Y1[128 + tid];
        ys0 = Y0[tid];       ys1 = Y1[tid];
    } else {
        ys0 = Y0[256 + (tid - 128)]; ys1 = Y1[256 + (tid - 128)];
    }

    float* cur = stA;
    float* nxt = stB;

    for (int t = 0; t < TT; t++) {
        // Issue next step's Y prefetch (hidden under ~2800-cyc step)
        int tn = (t + 1 < TT) ? (t + 1) : t;
        const float* y0p = Y0 + (size_t)tn * YW;
        const float* y1p = Y1 + (size_t)tn * YW;
        float nyv0 = 0.f, nyv1 = 0.f, nys0, nys1;
        if (tid < 128) {
            nyv0 = __ldg(y0p + 128 + tid); nyv1 = __ldg(y1p + 128 + tid);
            nys0 = __ldg(y0p + tid);       nys1 = __ldg(y1p + tid);
        } else {
            nys0 = __ldg(y0p + 256 + (tid - 128));
            nys1 = __ldg(y1p + 256 + (tid - 128));
        }

        // ---- Phase A: v = state @ CK2 + Yv ; z = 2*tanh(v) - v ----
        if (tid < 128) {
            float a0 = yv0, a1 = yv1;
            #pragma unroll 8
            for (int s = 0; s < 128; s += 2) {
                float4 sp = *(const float4*)&cur[2 * s];      // {st0[s],st1[s],st0[s+1],st1[s+1]}
                float w0 = CK2s[s * 128 + tid];
                float w1 = CK2s[(s + 1) * 128 + tid];
                a0 = fmaf(sp.x, w0, a0); a1 = fmaf(sp.y, w0, a1);
                a0 = fmaf(sp.z, w1, a0); a1 = fmaf(sp.w, w1, a1);
            }
            float z0 = 2.f * tanh_acc(a0) - a0;
            float z1 = 2.f * tanh_acc(a1) - a1;
            zs[2 * tid]     = z0;
            zs[2 * tid + 1] = z1;
        }
        __syncthreads();

        // ---- Phase BC: [new_state | u] = [state|z] @ W2 + [Ys|Yu] ----
        {
            float a0 = ys0, a1 = ys1;
            const float* W = W2 + tid;
            #pragma unroll 8
            for (int s = 0; s < 128; s += 2) {
                float4 sp = *(const float4*)&cur[2 * s];
                float w0 = W[s * 160];
                float w1 = W[(s + 1) * 160];
                a0 = fmaf(sp.x, w0, a0); a1 = fmaf(sp.y, w0, a1);
                a0 = fmaf(sp.z, w1, a0); a1 = fmaf(sp.w, w1, a1);
            }
            const float* Wz = W2 + 128 * 160 + tid;
            #pragma unroll 8
            for (int h = 0; h < 128; h += 2) {
                float4 zp = *(const float4*)&zs[2 * h];
                float w0 = Wz[h * 160];
                float w1 = Wz[(h + 1) * 160];
                a0 = fmaf(zp.x, w0, a0); a1 = fmaf(zp.y, w0, a1);
                a0 = fmaf(zp.z, w1, a0); a1 = fmaf(zp.w, w1, a1);
            }
            if (tid < 128) {
                nxt[2 * tid]     = a0;
                nxt[2 * tid + 1] = a1;
            } else {
                int a = tid - 128;
                size_t r0 = ((size_t)b0 * TT + t) * 64;
                size_t r1 = ((size_t)b1 * TT + t) * 64;
                out[r0 + a] = a0; out[r0 + 32 + a] = ls;
                out[r1 + a] = a1; out[r1 + 32 + a] = ls;
            }
        }
        __syncthreads();

        float* tmp = cur; cur = nxt; nxt = tmp;
        yv0 = nyv0; yv1 = nyv1; ys0 = nys0; ys1 = nys1;
    }

    // state_final
    if (tid < 128) {
        size_t base = (size_t)BATCH * TT * 64;
        out[base + b0 * 128 + tid] = cur[2 * tid];
        out[base + b1 * 128 + tid] = cur[2 * tid + 1];
    }
}

// ---------------------------------------------------------------------------
// kernel_launch
// Inputs (metadata order): obs, state0, AK_tT, BK1_tT, BK2_tT, CK1_tT,
//                          DK1_tT, DK2_tT, CK2_tT, DK3_tT, log_stds
// Output: outputs [B,T,64] then state_final [B,S], all f32.
// ---------------------------------------------------------------------------
extern "C" void kernel_launch(void* const* d_in, const int* in_sizes, int n_in,
                              void* d_out, int out_size)
{
    const float* obs    = (const float*)d_in[0];
    const float* state0 = (const float*)d_in[1];
    const float* AK     = (const float*)d_in[2];
    const float* BK1    = (const float*)d_in[3];
    const float* BK2    = (const float*)d_in[4];
    const float* CK1    = (const float*)d_in[5];
    const float* DK1    = (const float*)d_in[6];
    const float* DK2    = (const float*)d_in[7];
    const float* CK2    = (const float*)d_in[8];
    const float* DK3    = (const float*)d_in[9];
    const float* lstd   = (const float*)d_in[10];
    float* out = (float*)d_out;

    const int SMEM_PRE = (128 * 288 + 2 * 32 * 128) * 4;                 // 180224
    const int SMEM_RNN = (16384 + 40960 + 256 + 256 + 256) * 4;          // 232448

    cudaFuncSetAttribute(precompute_y_kernel,
                         cudaFuncAttributeMaxDynamicSharedMemorySize, SMEM_PRE);
    cudaFuncSetAttribute(rnn_seq_kernel,
                         cudaFuncAttributeMaxDynamicSharedMemorySize, SMEM_RNN);

    precompute_y_kernel<<<148, 288, SMEM_PRE>>>(obs, BK2, DK3, DK2);
    rnn_seq_kernel<<<BATCH / 2, 160, SMEM_RNN>>>(state0, AK, BK1, CK1, DK1,
                                                 CK2, lstd, out);
}

// round 3
// speedup vs baseline: 1.5264x; 1.5264x over previous
#include <cuda_runtime.h>
#include <cstdint>
#include <cstring>

#define BATCH 256
#define TT    2048
#define YW    288   // [0:128)=Ys (y@BK2), [128:256)=Yv (y@DK3), [256:288)=Yu (y@DK2)

typedef unsigned long long u64;

// 604 MB scratch for the time-parallel precompute
__device__ float g_Y[(size_t)BATCH * TT * YW];

// ---------------------------------------------------------------------------
// helpers
// ---------------------------------------------------------------------------
__device__ __forceinline__ void cp16(void* s, const void* g) {
    unsigned saddr = (unsigned)__cvta_generic_to_shared(s);
    asm volatile("cp.async.cg.shared.global [%0], [%1], 16;\n" :: "r"(saddr), "l"(g));
}
__device__ __forceinline__ void cp_commit() { asm volatile("cp.async.commit_group;\n"); }
__device__ __forceinline__ void cp_wait0()  { asm volatile("cp.async.wait_group 0;\n"); }

// packed f32x2 FMA: d = a*b + d  (Blackwell sm_100a)
__device__ __forceinline__ void ffma2(u64& d, u64 a, u64 b) {
    asm("fma.rn.f32x2 %0, %1, %2, %0;" : "+l"(d) : "l"(a), "l"(b));
}
__device__ __forceinline__ u64 packf2(float lo, float hi) {
    float2 t; t.x = lo; t.y = hi; u64 r; memcpy(&r, &t, 8); return r;
}
__device__ __forceinline__ float sum2(u64 v) {
    float2 t; memcpy(&t, &v, 8); return t.x + t.y;
}

// Accurate tanh independent of --use_fast_math: (e^{2v}-1)/(e^{2v}+1) via EX2
__device__ __forceinline__ float tanh_acc(float x) {
    float xc = fminf(fmaxf(x, -15.f), 15.f);
    float e  = exp2f(xc * 2.8853900817779268f);   // 2*log2(e)
    return (e - 1.f) / (e + 1.f);
}

// ---------------------------------------------------------------------------
// Kernel 1: Y[m][0:288] = obs[m][:] @ [BK2 | DK3 | DK2]^T
// W1 transposed+padded in smem; obs double-buffered; f32x2 FMA.
// 288 threads: thread n owns output column n, 32 rows per chunk.
// ---------------------------------------------------------------------------
__global__ __launch_bounds__(288, 1)
void precompute_y_kernel(const float* __restrict__ obs,
                         const float* __restrict__ BK2,
                         const float* __restrict__ DK3,
                         const float* __restrict__ DK2)
{
    extern __shared__ float sm[];
    float* W1T = sm;                  // [288][132]  (col-major: row n = weights of out-col n)
    float* ob0 = sm + 288 * 132;      // [32][128]
    float* ob1 = ob0 + 4096;

    const int tid = threadIdx.x;

    // Load W1 transposed (one-time)
    for (int idx = tid; idx < 288 * 128; idx += 288) {
        int n = idx >> 7, k = idx & 127;
        float v;
        if      (n < 128) v = BK2[k * 128 + n];
        else if (n < 256) v = DK3[k * 128 + (n - 128)];
        else              v = DK2[k * 32  + (n - 256)];
        W1T[n * 132 + k] = v;
    }

    const int NCH = (BATCH * TT) / 32;   // 16384 chunks of 32 rows
    int chunk = blockIdx.x;

    {   // prologue
        const float* src = obs + (size_t)chunk * 32 * 128;
        for (int i = tid; i < 1024; i += 288)
            cp16(&ob0[i * 4], &src[i * 4]);
        cp_commit(); cp_wait0();
    }
    __syncthreads();

    const int n = tid;
    const ulonglong2* w2 = (const ulonglong2*)(W1T + n * 132);

    int p = 0;
    for (; chunk < NCH; chunk += gridDim.x) {
        float* cur = p ? ob1 : ob0;
        float* nb  = p ? ob0 : ob1;
        int nxt = chunk + gridDim.x;
        if (nxt < NCH) {
            const float* src = obs + (size_t)nxt * 32 * 128;
            for (int i = tid; i < 1024; i += 288)
                cp16(&nb[i * 4], &src[i * 4]);
        }
        cp_commit();

        u64 acc[32];
        #pragma unroll
        for (int m = 0; m < 32; m++) acc[m] = 0ull;

        #pragma unroll 8
        for (int j = 0; j < 32; j++) {            // 4 k per iter
            ulonglong2 wv = w2[j];                // (w[4j],w[4j+1]) , (w[4j+2],w[4j+3])
            #pragma unroll
            for (int m = 0; m < 32; m++) {
                ulonglong2 o = *(const ulonglong2*)&cur[m * 128 + 4 * j];
                ffma2(acc[m], o.x, wv.x);
                ffma2(acc[m], o.y, wv.y);
            }
        }
        size_t base = (size_t)chunk * 32 * YW + n;
        #pragma unroll 4
        for (int m = 0; m < 32; m++)
            g_Y[base + (size_t)m * YW] = sum2(acc[m]);

        cp_wait0();
        __syncthreads();
        p ^= 1;
    }
}

// ---------------------------------------------------------------------------
// Kernel 2: sequential recurrence. 128 CTAs x 2 batch rows, 288 threads.
//   tid 0..127  (A):  v-col tid; CK2 column register-resident (64 x b64)
//   tid 128..287(BC): BC-col c=tid-128; z-phase weights register-resident;
//                     state-phase weights from smem (transposed, pad 132)
// Per step: stage1 {A: v,z | BC: state-part acc}; bar; stage2 {BC: z-part,
// write state/out}; bar.
// ---------------------------------------------------------------------------
__global__ __launch_bounds__(288, 1)
void rnn_seq_kernel(const float* __restrict__ state0,
                    const float* __restrict__ AK,
                    const float* __restrict__ BK1,
                    const float* __restrict__ CK1,
                    const float* __restrict__ DK1,
                    const float* __restrict__ CK2,
                    const float* __restrict__ logstd,
                    float* __restrict__ out)
{
    extern __shared__ float sm[];
    float* W2sT = sm;                    // [160][132]  state-phase weights (transposed)
    float* st   = W2sT + 160 * 132;      // 2 bufs x (row0[128], row1[128])
    float* zz   = st + 512;              // row0[128], row1[128]

    const int tid = threadIdx.x;
    const int b0 = blockIdx.x * 2, b1 = b0 + 1;

    // smem: state-phase weights [AK | CK1], transposed by output column
    for (int idx = tid; idx < 160 * 128; idx += 288) {
        int c = idx >> 7, k = idx & 127;
        float v = (c < 128) ? AK[k * 128 + c] : CK1[k * 32 + (c - 128)];
        W2sT[c * 132 + k] = v;
    }

    // register weights (role-dependent): A -> CK2 column; BC -> [BK1|DK1] column
    u64 wreg[64];
    if (tid < 128) {
        #pragma unroll
        for (int i = 0; i < 64; i++)
            wreg[i] = packf2(CK2[(2 * i) * 128 + tid], CK2[(2 * i + 1) * 128 + tid]);
    } else {
        int c = tid - 128;
        #pragma unroll
        for (int i = 0; i < 64; i++) {
            float lo, hi;
            if (c < 128) { lo = BK1[(2 * i) * 128 + c];        hi = BK1[(2 * i + 1) * 128 + c]; }
            else         { lo = DK1[(2 * i) * 32 + (c - 128)]; hi = DK1[(2 * i + 1) * 32 + (c - 128)]; }
            wreg[i] = packf2(lo, hi);
        }
    }

    if (tid < 128) {
        st[tid]       = state0[b0 * 128 + tid];
        st[128 + tid] = state0[b1 * 128 + tid];
    }
    float ls = (tid >= 256) ? logstd[tid - 256] : 0.f;

    // Y column this thread consumes each step
    int yidx;
    if (tid < 128)      yidx = 128 + tid;        // Yv
    else if (tid < 256) yidx = tid - 128;        // Ys
    else                yidx = tid;              // Yu (=128+c)
    const float* Y0 = g_Y + (size_t)b0 * TT * YW + yidx;
    const float* Y1 = g_Y + (size_t)b1 * TT * YW + yidx;

    __syncthreads();

    float y0 = __ldg(Y0), y1 = __ldg(Y1);
    float* cur = st;
    float* nxt = st + 256;

    for (int t = 0; t < TT; t++) {
        // prefetch next step's Y under this step's compute
        int tn = (t + 1 < TT) ? (t + 1) : t;
        float ny0 = __ldg(Y0 + (size_t)tn * YW);
        float ny1 = __ldg(Y1 + (size_t)tn * YW);

        u64 a0a = 0, a0b = 0, a1a = 0, a1b = 0;
        const ulonglong2* s0 = (const ulonglong2*)cur;
        const ulonglong2* s1 = (const ulonglong2*)(cur + 128);

        if (tid < 128) {
            // stage 1 (A): v = state @ CK2 + yv ; z = 2 tanh(v) - v
            #pragma unroll
            for (int j = 0; j < 32; j++) {
                ulonglong2 a = s0[j], b = s1[j];
                ffma2(a0a, a.x, wreg[2 * j]);
                ffma2(a0b, a.y, wreg[2 * j + 1]);
                ffma2(a1a, b.x, wreg[2 * j]);
                ffma2(a1b, b.y, wreg[2 * j + 1]);
            }
            float v0 = y0 + sum2(a0a) + sum2(a0b);
            float v1 = y1 + sum2(a1a) + sum2(a1b);
            zz[tid]       = 2.f * tanh_acc(v0) - v0;
            zz[128 + tid] = 2.f * tanh_acc(v1) - v1;
        } else {
            // stage 1 (BC): acc = state @ [AK|CK1]  (weights from smem)
            int c = tid - 128;
            const ulonglong2* w = (const ulonglong2*)(W2sT + c * 132);
            #pragma unroll
            for (int j = 0; j < 32; j++) {
                ulonglong2 wv = w[j];
                ulonglong2 a = s0[j], b = s1[j];
                ffma2(a0a, a.x, wv.x);
                ffma2(a0b, a.y, wv.y);
                ffma2(a1a, b.x, wv.x);
                ffma2(a1b, b.y, wv.y);
            }
        }
        __syncthreads();

        if (tid >= 128) {
            // stage 2 (BC): acc += z @ [BK1|DK1]  (weights from registers)
            const ulonglong2* z0 = (const ulonglong2*)zz;
            const ulonglong2* z1 = (const ulonglong2*)(zz + 128);
            #pragma unroll
            for (int j = 0; j < 32; j++) {
                ulonglong2 a = z0[j], b = z1[j];
                ffma2(a0a, a.x, wreg[2 * j]);
                ffma2(a0b, a.y, wreg[2 * j + 1]);
                ffma2(a1a, b.x, wreg[2 * j]);
                ffma2(a1b, b.y, wreg[2 * j + 1]);
            }
            float r0 = y0 + sum2(a0a) + sum2(a0b);
            float r1 = y1 + sum2(a1a) + sum2(a1b);
            int c = tid - 128;
            if (c < 128) {
                nxt[c]       = r0;
                nxt[128 + c] = r1;
            } else {
                int a = c - 128;
                size_t o0 = ((size_t)b0 * TT + t) * 64;
                size_t o1 = ((size_t)b1 * TT + t) * 64;
                out[o0 + a] = r0; out[o0 + 32 + a] = ls;
                out[o1 + a] = r1; out[o1 + 32 + a] = ls;
            }
        }
        __syncthreads();

        float* tmp = cur; cur = nxt; nxt = tmp;
        y0 = ny0; y1 = ny1;
    }

    if (tid < 128) {
        size_t base = (size_t)BATCH * TT * 64;
        out[base + b0 * 128 + tid] = cur[tid];
        out[base + b1 * 128 + tid] = cur[128 + tid];
    }
}

// ---------------------------------------------------------------------------
// kernel_launch
// Inputs: obs, state0, AK_tT, BK1_tT, BK2_tT, CK1_tT, DK1_tT, DK2_tT,
//         CK2_tT, DK3_tT, log_stds
// ---------------------------------------------------------------------------
extern "C" void kernel_launch(void* const* d_in, const int* in_sizes, int n_in,
                              void* d_out, int out_size)
{
    const float* obs    = (const float*)d_in[0];
    const float* state0 = (const float*)d_in[1];
    const float* AK     = (const float*)d_in[2];
    const float* BK1    = (const float*)d_in[3];
    const float* BK2    = (const float*)d_in[4];
    const float* CK1    = (const float*)d_in[5];
    const float* DK1    = (const float*)d_in[6];
    const float* DK2    = (const float*)d_in[7];
    const float* CK2    = (const float*)d_in[8];
    const float* DK3    = (const float*)d_in[9];
    const float* lstd   = (const float*)d_in[10];
    float* out = (float*)d_out;

    const int SMEM_PRE = (288 * 132 + 2 * 4096) * 4;            // 184832
    const int SMEM_RNN = (160 * 132 + 512 + 256) * 4;           // 87552

    cudaFuncSetAttribute(precompute_y_kernel,
                         cudaFuncAttributeMaxDynamicSharedMemorySize, SMEM_PRE);
    cudaFuncSetAttribute(rnn_seq_kernel,
                         cudaFuncAttributeMaxDynamicSharedMemorySize, SMEM_RNN);

    precompute_y_kernel<<<148, 288, SMEM_PRE>>>(obs, BK2, DK3, DK2);
    rnn_seq_kernel<<<BATCH / 2, 288, SMEM_RNN>>>(state0, AK, BK1, CK1, DK1,
                                                 CK2, lstd, out);
}